// round 9
// baseline (speedup 1.0000x reference)
#include <cuda_runtime.h>
#include <cstdint>

#define N_PTS 20000
#define N_PAD 20480          // 64*320: clean tiling for dist/select
#define E_EDG 320000
#define ROWBLK 2560          // query rows per dist/select pass
#define NBLK 8               // 8*2560 == N_PAD
#define QTILES 40            // ROWBLK/64
#define KTILES 320           // N_PAD/64

// ---------------- device scratch (no allocations allowed) ----------------
__device__ float g_x1[N_PAD * 64];            // node features after stage 1 (pad rows = 0)
__device__ float g_sq[N_PAD];                 // squared norms (pad = 1e30)
__device__ float g_D[(size_t)ROWBLK * N_PAD]; // distance row-block (210 MB)
__device__ int   g_nbr[N_PTS * 16];           // knn indices
__device__ float g_x2[N_PTS * 64];            // stage-2 features
__device__ float g_xs[N_PTS * 4 * 64];        // xe reshaped/transposed rows
__device__ float g_feat[N_PTS * 4 * 64];      // feat = xs@Wp+bp

// packed fp32x2 helpers (Blackwell FFMA2 path)
__device__ __forceinline__ unsigned long long ffma2(unsigned long long a,
                                                    unsigned long long b,
                                                    unsigned long long c) {
    unsigned long long d;
    asm("fma.rn.f32x2 %0, %1, %2, %3;" : "=l"(d) : "l"(a), "l"(b), "l"(c));
    return d;
}
__device__ __forceinline__ void unpack2(float& lo, float& hi, unsigned long long v) {
    asm("mov.b64 {%0, %1}, %2;" : "=f"(lo), "=f"(hi) : "l"(v));
}

// ---------------- zero x1 (incl. pad rows) ----------------
__global__ void k_zero() {
    int i = blockIdx.x * blockDim.x + threadIdx.x;   // 1280*256 == N_PAD*64/4 exactly
    ((float4*)g_x1)[i] = make_float4(0.f, 0.f, 0.f, 0.f);
}

// ---------------- stage 1: edge MLP (6->64 relu ->64 relu) + segment max ----------------
__global__ void __launch_bounds__(256) k_edge(const float* __restrict__ dep,
                                              const int*   __restrict__ ei,
                                              const float* __restrict__ W1a,
                                              const float* __restrict__ b1a,
                                              const float* __restrict__ W1b,
                                              const float* __restrict__ b1b) {
    __shared__ float sW1a[6 * 64];
    __shared__ float sW1b[64 * 64];
    __shared__ float sb1a[64];
    __shared__ float sb1b[64];
    int tid = threadIdx.x;
    for (int m = tid; m < 6 * 64; m += 256) sW1a[m] = W1a[m];
    for (int m = tid; m < 64 * 64; m += 256) sW1b[m] = W1b[m];
    if (tid < 64) { sb1a[tid] = b1a[tid]; sb1b[tid] = b1b[tid]; }
    __syncthreads();

    int e = blockIdx.x * 256 + tid;                 // grid 1250*256 == E exactly
    int s = ei[e];
    int d = ei[E_EDG + e];
    float xi0 = dep[d * 3], xi1 = dep[d * 3 + 1], xi2 = dep[d * 3 + 2];
    float in6[6];
    in6[0] = xi0; in6[1] = xi1; in6[2] = xi2;
    in6[3] = dep[s * 3] - xi0; in6[4] = dep[s * 3 + 1] - xi1; in6[5] = dep[s * 3 + 2] - xi2;

    float h[64];
#pragma unroll
    for (int f = 0; f < 64; f++) h[f] = sb1a[f];
#pragma unroll
    for (int k = 0; k < 6; k++) {
        float v = in6[k];
#pragma unroll
        for (int f4 = 0; f4 < 16; f4++) {
            float4 w = ((const float4*)sW1a)[k * 16 + f4];
            h[f4 * 4 + 0] += v * w.x; h[f4 * 4 + 1] += v * w.y;
            h[f4 * 4 + 2] += v * w.z; h[f4 * 4 + 3] += v * w.w;
        }
    }
#pragma unroll
    for (int f = 0; f < 64; f++) h[f] = fmaxf(h[f], 0.f);

    int* outp = (int*)(g_x1 + (size_t)d * 64);
    for (int c = 0; c < 4; c++) {                   // 16-wide output chunks
        float o[16];
#pragma unroll
        for (int m = 0; m < 16; m++) o[m] = sb1b[c * 16 + m];
#pragma unroll
        for (int k = 0; k < 64; k++) {
            float hk = h[k];
#pragma unroll
            for (int q = 0; q < 4; q++) {
                float4 w = ((const float4*)sW1b)[k * 16 + c * 4 + q];
                o[q * 4 + 0] += hk * w.x; o[q * 4 + 1] += hk * w.y;
                o[q * 4 + 2] += hk * w.z; o[q * 4 + 3] += hk * w.w;
            }
        }
#pragma unroll
        for (int m = 0; m < 16; m++) {
            float v = fmaxf(o[m], 0.f);             // relu => v >= 0 => int-compare valid
            atomicMax(outp + c * 16 + m, __float_as_int(v));
        }
    }
}

// ---------------- squared norms ----------------
__global__ void k_sq() {
    int i = blockIdx.x * blockDim.x + threadIdx.x;   // 80*256 == N_PAD
    if (i >= N_PTS) { g_sq[i] = 1e30f; return; }     // pad keys never selected
    const float4* p = (const float4*)(g_x1 + (size_t)i * 64);
    float s = 0.f;
#pragma unroll
    for (int k = 0; k < 16; k++) { float4 v = p[k]; s += v.x * v.x + v.y * v.y + v.z * v.z + v.w * v.w; }
    g_sq[i] = s;
}

// ---------------- KNN stage A: distance row-block GEMM (FFMA2, 64x64 tile) ----------------
// block 256 thr = 16x16; thread (x,y) computes q rows {4y..4y+3} x k cols {x,x+16,x+32,x+48}
__global__ void __launch_bounds__(256) k_dist(int qbase) {
    __shared__ __align__(16) float sQ[64][68];
    __shared__ __align__(16) float sK[64][68];
    __shared__ float sqq[64], sqk[64];

    const int tid = threadIdx.x;
    const int qrow0 = qbase + blockIdx.x * 64;
    const int krow0 = blockIdx.y * 64;

#pragma unroll
    for (int m = 0; m < 4; m++) {
        int idx = m * 256 + tid;                    // 1024 float4
        int r = idx >> 4, c = idx & 15;
        *(float4*)(&sQ[r][c * 4]) = ((const float4*)g_x1)[(size_t)(qrow0 + r) * 16 + c];
        *(float4*)(&sK[r][c * 4]) = ((const float4*)g_x1)[(size_t)(krow0 + r) * 16 + c];
    }
    if (tid < 64) sqq[tid] = g_sq[qrow0 + tid];
    else if (tid < 128) sqk[tid - 64] = g_sq[krow0 + tid - 64];
    __syncthreads();

    const int x = tid & 15;
    const int y = tid >> 4;

    unsigned long long acc[4][4];
#pragma unroll
    for (int i = 0; i < 4; i++)
#pragma unroll
        for (int j = 0; j < 4; j++) acc[i][j] = 0ull;

#pragma unroll 4
    for (int s = 0; s < 16; s++) {                  // 4 features per step
        ulonglong2 qv[4], kv[4];
#pragma unroll
        for (int i = 0; i < 4; i++) qv[i] = *(const ulonglong2*)(&sQ[4 * y + i][4 * s]);
#pragma unroll
        for (int j = 0; j < 4; j++) kv[j] = *(const ulonglong2*)(&sK[x + 16 * j][4 * s]);
#pragma unroll
        for (int i = 0; i < 4; i++)
#pragma unroll
            for (int j = 0; j < 4; j++) {
                acc[i][j] = ffma2(qv[i].x, kv[j].x, acc[i][j]);
                acc[i][j] = ffma2(qv[i].y, kv[j].y, acc[i][j]);
            }
    }

#pragma unroll
    for (int i = 0; i < 4; i++) {
        const float si = sqq[4 * y + i];
        float* drow = g_D + (size_t)(blockIdx.x * 64 + 4 * y + i) * N_PAD + krow0;
#pragma unroll
        for (int j = 0; j < 4; j++) {
            float lo, hi; unpack2(lo, hi, acc[i][j]);
            drow[x + 16 * j] = fmaf(-2.f, lo + hi, si + sqk[x + 16 * j]);
        }
    }
}

// ---------------- KNN stage B: exact top-16 per row from materialized D ----------------
// 512 thr = 16 warps; one warp per row; lane streams float4 chunks l, l+32, ...
__global__ void __launch_bounds__(512) k_select(int qbase) {
    const int tid  = threadIdx.x;
    const int lane = tid & 31;
    const int w    = tid >> 5;
    const int rl   = blockIdx.x * 16 + w;        // local row in D
    const int gi   = qbase + rl;
    if (gi >= N_PTS) return;                     // warp-uniform exit

    const float4* Dp = (const float4*)(g_D + (size_t)rl * N_PAD);

    unsigned long long best[16];
#pragma unroll
    for (int m = 0; m < 16; m++) best[m] = 0xFF7FFFFFFFFFFFFFull;  // (FLT_MAX, ~0)
    unsigned long long worst_key = 0xFF7FFFFFFFFFFFFFull;
    float worst_f = 3.4e38f;
    float gate_f  = 3.4e38f;

    for (int c = 0; c < 160; c++) {              // 160*32 = 5120 float4 = N_PAD floats
        if ((c & 7) == 0) {                      // refresh warp gate (upper bound of row 16th)
            float g = worst_f;
#pragma unroll
            for (int d = 1; d < 32; d <<= 1) g = fminf(g, __shfl_xor_sync(0xFFFFFFFFu, g, d));
            gate_f = g;
        }
        float4 v = Dp[lane + 32 * c];
        const int jb = 4 * (lane + 32 * c);
        float e[4] = {v.x, v.y, v.z, v.w};
#pragma unroll
        for (int q = 0; q < 4; q++) {
            if (e[q] <= gate_f) {
                unsigned int b = __float_as_uint(e[q]);
                b ^= (unsigned int)((int)b >> 31) | 0x80000000u;   // sortable
                unsigned long long key = ((unsigned long long)b << 32) | (unsigned int)(jb + q);
                if (key < worst_key) {
                    // evict current max
                    unsigned long long mv = best[0]; int slot = 0;
#pragma unroll
                    for (int m = 1; m < 16; m++) if (best[m] > mv) { mv = best[m]; slot = m; }
#pragma unroll
                    for (int m = 0; m < 16; m++) if (m == slot) best[m] = key;
                    unsigned long long wk = best[0];
#pragma unroll
                    for (int m = 1; m < 16; m++) wk = (best[m] > wk) ? best[m] : wk;
                    worst_key = wk;
                    unsigned int u = (unsigned int)(wk >> 32);
                    u = (u & 0x80000000u) ? (u ^ 0x80000000u) : ~u;
                    worst_f = __uint_as_float(u);
                }
            }
        }
    }

    // merge 32 lanes' lists -> row top-16 (keys unique: j disjoint per lane)
    for (int sel = 0; sel < 16; sel++) {
        unsigned long long mn = best[0]; int ms = 0;
#pragma unroll
        for (int m = 1; m < 16; m++) if (best[m] < mn) { mn = best[m]; ms = m; }
        unsigned long long gm = mn;
#pragma unroll
        for (int d = 1; d < 32; d <<= 1) {
            unsigned long long o = __shfl_xor_sync(0xFFFFFFFFu, gm, d);
            gm = (o < gm) ? o : gm;
        }
        if (gm == mn) {
#pragma unroll
            for (int m = 0; m < 16; m++) if (m == ms) best[m] = 0xFFFFFFFFFFFFFFFFull;
        }
        if (lane == 0) g_nbr[gi * 16 + sel] = (int)(unsigned int)(gm & 0xFFFFFFFFull);
    }
}

// ---------------- stage 2: edgeconv (128->64 relu ->64 relu), max over 16 neighbors ----------------
__global__ void __launch_bounds__(128) k_conv2(const float* __restrict__ W2a,
                                               const float* __restrict__ b2a,
                                               const float* __restrict__ W2b,
                                               const float* __restrict__ b2b) {
    __shared__ float sW2a[128 * 64];    // 32 KB
    __shared__ float sW2b[64 * 64];     // 16 KB
    int tid = threadIdx.x;
    for (int m = tid; m < 128 * 64; m += 128) sW2a[m] = W2a[m];
    for (int m = tid; m < 64 * 64;  m += 128) sW2b[m] = W2b[m];
    __syncthreads();

    int gid = blockIdx.x * 128 + tid;   // 2500*128 == 320000 exactly
    int i  = gid >> 4;
    int jn = gid & 15;
    int j  = g_nbr[i * 16 + jn];
    const float4* xi4 = (const float4*)(g_x1 + (size_t)i * 64);
    const float4* xj4 = (const float4*)(g_x1 + (size_t)j * 64);

    float h[64];
#pragma unroll
    for (int f = 0; f < 64; f++) h[f] = __ldg(&b2a[f]);

#pragma unroll 4
    for (int k4 = 0; k4 < 16; k4++) {
        float4 A = xi4[k4], B = xj4[k4];
        float av[4] = {A.x, A.y, A.z, A.w};
        float dv[4] = {B.x - A.x, B.y - A.y, B.z - A.z, B.w - A.w};
#pragma unroll
        for (int s = 0; s < 4; s++) {
            int k = k4 * 4 + s;
            float a = av[s], dd = dv[s];
#pragma unroll
            for (int f4 = 0; f4 < 16; f4++) {
                float4 w1 = ((const float4*)sW2a)[k * 16 + f4];
                float4 w2 = ((const float4*)sW2a)[(64 + k) * 16 + f4];
                h[f4 * 4 + 0] += a * w1.x + dd * w2.x;
                h[f4 * 4 + 1] += a * w1.y + dd * w2.y;
                h[f4 * 4 + 2] += a * w1.z + dd * w2.z;
                h[f4 * 4 + 3] += a * w1.w + dd * w2.w;
            }
        }
    }
#pragma unroll
    for (int f = 0; f < 64; f++) h[f] = fmaxf(h[f], 0.f);

    for (int c = 0; c < 4; c++) {
        float o[16];
#pragma unroll
        for (int m = 0; m < 16; m++) o[m] = __ldg(&b2b[c * 16 + m]);
#pragma unroll
        for (int k = 0; k < 64; k++) {
            float hk = h[k];
#pragma unroll
            for (int q = 0; q < 4; q++) {
                float4 w = ((const float4*)sW2b)[k * 16 + c * 4 + q];
                o[q * 4 + 0] += hk * w.x; o[q * 4 + 1] += hk * w.y;
                o[q * 4 + 2] += hk * w.z; o[q * 4 + 3] += hk * w.w;
            }
        }
#pragma unroll
        for (int m = 0; m < 16; m++) {
            float v = fmaxf(o[m], 0.f);                              // relu before max
            v = fmaxf(v, __shfl_xor_sync(0xFFFFFFFFu, v, 1, 16));    // max over 16 neighbors
            v = fmaxf(v, __shfl_xor_sync(0xFFFFFFFFu, v, 2, 16));
            v = fmaxf(v, __shfl_xor_sync(0xFFFFFFFFu, v, 4, 16));
            v = fmaxf(v, __shfl_xor_sync(0xFFFFFFFFu, v, 8, 16));
            o[m] = v;
        }
        if (jn == 0) {
            float4* dst = (float4*)(g_x2 + (size_t)i * 64 + c * 16);
            dst[0] = make_float4(o[0],  o[1],  o[2],  o[3]);
            dst[1] = make_float4(o[4],  o[5],  o[6],  o[7]);
            dst[2] = make_float4(o[8],  o[9],  o[10], o[11]);
            dst[3] = make_float4(o[12], o[13], o[14], o[15]);
        }
    }
}

// ---------------- xe = x2 @ We + be, transposed-store per (i, r) ----------------
__global__ void __launch_bounds__(256) k_lin1(const float* __restrict__ We,
                                              const float* __restrict__ be) {
    __shared__ float sW[64 * 64];
    __shared__ float sb[64];
    int r = blockIdx.y, tid = threadIdx.x;
    for (int m = tid; m < 4096; m += 256) {
        int k = m >> 6, c = m & 63;
        sW[m] = We[k * 256 + r * 64 + c];
    }
    if (tid < 64) sb[tid] = be[r * 64 + tid];
    __syncthreads();

    int i = blockIdx.x * 256 + tid;
    if (i >= N_PTS) return;
    float x[64];
    const float4* xp = (const float4*)(g_x2 + (size_t)i * 64);
#pragma unroll
    for (int k4 = 0; k4 < 16; k4++) {
        float4 v = xp[k4];
        x[k4 * 4 + 0] = v.x; x[k4 * 4 + 1] = v.y; x[k4 * 4 + 2] = v.z; x[k4 * 4 + 3] = v.w;
    }
    float* outp = g_xs + ((size_t)r * N_PTS + i) * 64;
    for (int c = 0; c < 4; c++) {
        float o[16];
#pragma unroll
        for (int m = 0; m < 16; m++) o[m] = sb[c * 16 + m];
#pragma unroll
        for (int k = 0; k < 64; k++) {
            float xk = x[k];
#pragma unroll
            for (int q = 0; q < 4; q++) {
                float4 w = ((const float4*)sW)[k * 16 + c * 4 + q];
                o[q * 4 + 0] += xk * w.x; o[q * 4 + 1] += xk * w.y;
                o[q * 4 + 2] += xk * w.z; o[q * 4 + 3] += xk * w.w;
            }
        }
        float4* op = (float4*)(outp + c * 16);
        op[0] = make_float4(o[0],  o[1],  o[2],  o[3]);
        op[1] = make_float4(o[4],  o[5],  o[6],  o[7]);
        op[2] = make_float4(o[8],  o[9],  o[10], o[11]);
        op[3] = make_float4(o[12], o[13], o[14], o[15]);
    }
}

// ---------------- feat = xs @ Wp + bp ----------------
__global__ void __launch_bounds__(256) k_feat(const float* __restrict__ Wp,
                                              const float* __restrict__ bp) {
    __shared__ float sW[64 * 64];
    __shared__ float sb[64];
    int tid = threadIdx.x;
    for (int m = tid; m < 4096; m += 256) sW[m] = Wp[m];
    if (tid < 64) sb[tid] = bp[tid];
    __syncthreads();
    int i = blockIdx.x * 256 + tid;
    if (i >= N_PTS * 4) return;
    float x[64];
    const float4* xp = (const float4*)(g_xs + (size_t)i * 64);
#pragma unroll
    for (int k4 = 0; k4 < 16; k4++) {
        float4 v = xp[k4];
        x[k4 * 4 + 0] = v.x; x[k4 * 4 + 1] = v.y; x[k4 * 4 + 2] = v.z; x[k4 * 4 + 3] = v.w;
    }
    float* outp = g_feat + (size_t)i * 64;
    for (int c = 0; c < 4; c++) {
        float o[16];
#pragma unroll
        for (int m = 0; m < 16; m++) o[m] = sb[c * 16 + m];
#pragma unroll
        for (int k = 0; k < 64; k++) {
            float xk = x[k];
#pragma unroll
            for (int q = 0; q < 4; q++) {
                float4 w = ((const float4*)sW)[k * 16 + c * 4 + q];
                o[q * 4 + 0] += xk * w.x; o[q * 4 + 1] += xk * w.y;
                o[q * 4 + 2] += xk * w.z; o[q * 4 + 3] += xk * w.w;
            }
        }
        float4* op = (float4*)(outp + c * 16);
        op[0] = make_float4(o[0],  o[1],  o[2],  o[3]);
        op[1] = make_float4(o[4],  o[5],  o[6],  o[7]);
        op[2] = make_float4(o[8],  o[9],  o[10], o[11]);
        op[3] = make_float4(o[12], o[13], o[14], o[15]);
    }
}

// ---------------- head: h = relu(feat@Wr1+br1); out = h@Wr2 + br2 ----------------
__global__ void __launch_bounds__(256) k_head(float* __restrict__ out,
                                              const float* __restrict__ Wr1,
                                              const float* __restrict__ br1,
                                              const float* __restrict__ Wr2,
                                              const float* __restrict__ br2) {
    __shared__ float sW[64 * 64];
    __shared__ float sb[64];
    __shared__ float sW2[64 * 3];
    __shared__ float sb2[3];
    int tid = threadIdx.x;
    for (int m = tid; m < 4096; m += 256) sW[m] = Wr1[m];
    if (tid < 64) sb[tid] = br1[tid];
    if (tid < 192) sW2[tid] = Wr2[tid];
    if (tid < 3) sb2[tid] = br2[tid];
    __syncthreads();
    int i = blockIdx.x * 256 + tid;
    if (i >= N_PTS * 4) return;
    float x[64];
    const float4* xp = (const float4*)(g_feat + (size_t)i * 64);
#pragma unroll
    for (int k4 = 0; k4 < 16; k4++) {
        float4 v = xp[k4];
        x[k4 * 4 + 0] = v.x; x[k4 * 4 + 1] = v.y; x[k4 * 4 + 2] = v.z; x[k4 * 4 + 3] = v.w;
    }
    float o0 = sb2[0], o1 = sb2[1], o2 = sb2[2];
    for (int c = 0; c < 4; c++) {
        float o[16];
#pragma unroll
        for (int m = 0; m < 16; m++) o[m] = sb[c * 16 + m];
#pragma unroll
        for (int k = 0; k < 64; k++) {
            float xk = x[k];
#pragma unroll
            for (int q = 0; q < 4; q++) {
                float4 w = ((const float4*)sW)[k * 16 + c * 4 + q];
                o[q * 4 + 0] += xk * w.x; o[q * 4 + 1] += xk * w.y;
                o[q * 4 + 2] += xk * w.z; o[q * 4 + 3] += xk * w.w;
            }
        }
#pragma unroll
        for (int m = 0; m < 16; m++) {
            float hm = fmaxf(o[m], 0.f);
            int jrow = c * 16 + m;
            o0 += hm * sW2[jrow * 3 + 0];
            o1 += hm * sW2[jrow * 3 + 1];
            o2 += hm * sW2[jrow * 3 + 2];
        }
    }
    out[(size_t)i * 3 + 0] = o0;
    out[(size_t)i * 3 + 1] = o1;
    out[(size_t)i * 3 + 2] = o2;
}

// ---------------- launch ----------------
extern "C" void kernel_launch(void* const* d_in, const int* in_sizes, int n_in,
                              void* d_out, int out_size) {
    const float* dep = (const float*)d_in[0];
    const float* W1a = (const float*)d_in[1];
    const float* b1a = (const float*)d_in[2];
    const float* W1b = (const float*)d_in[3];
    const float* b1b = (const float*)d_in[4];
    const float* W2a = (const float*)d_in[5];
    const float* b2a = (const float*)d_in[6];
    const float* W2b = (const float*)d_in[7];
    const float* b2b = (const float*)d_in[8];
    const float* We  = (const float*)d_in[9];
    const float* be  = (const float*)d_in[10];
    const float* Wp  = (const float*)d_in[11];
    const float* bp  = (const float*)d_in[12];
    const float* Wr1 = (const float*)d_in[13];
    const float* br1 = (const float*)d_in[14];
    const float* Wr2 = (const float*)d_in[15];
    const float* br2 = (const float*)d_in[16];
    const int*   ei  = (const int*)d_in[17];
    float* out = (float*)d_out;

    k_zero<<<1280, 256>>>();                               // N_PAD*64/4 threads
    k_edge<<<1250, 256>>>(dep, ei, W1a, b1a, W1b, b1b);    // E threads exactly
    k_sq<<<80, 256>>>();                                   // N_PAD threads
    for (int b = 0; b < NBLK; b++) {
        k_dist<<<dim3(QTILES, KTILES), 256>>>(b * ROWBLK);
        k_select<<<ROWBLK / 16, 512>>>(b * ROWBLK);
    }
    k_conv2<<<2500, 128>>>(W2a, b2a, W2b, b2b);            // N*16 threads exactly
    k_lin1<<<dim3((N_PTS + 255) / 256, 4), 256>>>(We, be);
    k_feat<<<(N_PTS * 4 + 255) / 256, 256>>>(Wp, bp);
    k_head<<<(N_PTS * 4 + 255) / 256, 256>>>(out, Wr1, br1, Wr2, br2);
    (void)in_sizes; (void)n_in; (void)out_size;
}

// round 10
// speedup vs baseline: 2.2939x; 2.2939x over previous
#include <cuda_runtime.h>
#include <cstdint>

#define N_PTS 20000
#define N_PAD 20480          // 64*320: clean tiling for dist/select
#define E_EDG 320000
#define ROWBLK 2560          // query rows per dist/select pass
#define NBLK 8               // 8*2560 == N_PAD
#define QT2 40               // ROWBLK/64  (q tiles per dist launch)
#define KT2 160              // N_PAD/128  (k tiles per dist launch)
#define SCAP 1024            // per-warp candidate buffer

// ---------------- device scratch (no allocations allowed) ----------------
__device__ float g_x1[N_PAD * 64];            // node features after stage 1 (pad rows = 0)
__device__ float g_sq[N_PAD];                 // squared norms (pad = 1e30)
__device__ float g_D[(size_t)ROWBLK * N_PAD]; // distance row-block (210 MB)
__device__ int   g_nbr[N_PTS * 16];           // knn indices
__device__ float g_x2[N_PTS * 64];            // stage-2 features
__device__ float g_xs[N_PTS * 4 * 64];        // xe reshaped/transposed rows
__device__ float g_feat[N_PTS * 4 * 64];      // feat = xs@Wp+bp

// packed fp32x2 helpers (Blackwell FFMA2 path)
__device__ __forceinline__ unsigned long long ffma2(unsigned long long a,
                                                    unsigned long long b,
                                                    unsigned long long c) {
    unsigned long long d;
    asm("fma.rn.f32x2 %0, %1, %2, %3;" : "=l"(d) : "l"(a), "l"(b), "l"(c));
    return d;
}
__device__ __forceinline__ void unpack2(float& lo, float& hi, unsigned long long v) {
    asm("mov.b64 {%0, %1}, %2;" : "=f"(lo), "=f"(hi) : "l"(v));
}
// float <-> sortable-uint (exact order, handles negatives)
__device__ __forceinline__ unsigned sortable(float f) {
    unsigned b = __float_as_uint(f);
    return b ^ ((unsigned)((int)b >> 31) | 0x80000000u);
}
__device__ __forceinline__ float unsortable(unsigned u) {
    u = (u & 0x80000000u) ? (u ^ 0x80000000u) : ~u;
    return __uint_as_float(u);
}

// ---------------- zero x1 (incl. pad rows) ----------------
__global__ void k_zero() {
    int i = blockIdx.x * blockDim.x + threadIdx.x;   // 1280*256 == N_PAD*64/4 exactly
    ((float4*)g_x1)[i] = make_float4(0.f, 0.f, 0.f, 0.f);
}

// ---------------- stage 1: edge MLP (6->64 relu ->64 relu) + segment max ----------------
__global__ void __launch_bounds__(256) k_edge(const float* __restrict__ dep,
                                              const int*   __restrict__ ei,
                                              const float* __restrict__ W1a,
                                              const float* __restrict__ b1a,
                                              const float* __restrict__ W1b,
                                              const float* __restrict__ b1b) {
    __shared__ float sW1a[6 * 64];
    __shared__ float sW1b[64 * 64];
    __shared__ float sb1a[64];
    __shared__ float sb1b[64];
    int tid = threadIdx.x;
    for (int m = tid; m < 6 * 64; m += 256) sW1a[m] = W1a[m];
    for (int m = tid; m < 64 * 64; m += 256) sW1b[m] = W1b[m];
    if (tid < 64) { sb1a[tid] = b1a[tid]; sb1b[tid] = b1b[tid]; }
    __syncthreads();

    int e = blockIdx.x * 256 + tid;                 // grid 1250*256 == E exactly
    int s = ei[e];
    int d = ei[E_EDG + e];
    float xi0 = dep[d * 3], xi1 = dep[d * 3 + 1], xi2 = dep[d * 3 + 2];
    float in6[6];
    in6[0] = xi0; in6[1] = xi1; in6[2] = xi2;
    in6[3] = dep[s * 3] - xi0; in6[4] = dep[s * 3 + 1] - xi1; in6[5] = dep[s * 3 + 2] - xi2;

    float h[64];
#pragma unroll
    for (int f = 0; f < 64; f++) h[f] = sb1a[f];
#pragma unroll
    for (int k = 0; k < 6; k++) {
        float v = in6[k];
#pragma unroll
        for (int f4 = 0; f4 < 16; f4++) {
            float4 w = ((const float4*)sW1a)[k * 16 + f4];
            h[f4 * 4 + 0] += v * w.x; h[f4 * 4 + 1] += v * w.y;
            h[f4 * 4 + 2] += v * w.z; h[f4 * 4 + 3] += v * w.w;
        }
    }
#pragma unroll
    for (int f = 0; f < 64; f++) h[f] = fmaxf(h[f], 0.f);

    int* outp = (int*)(g_x1 + (size_t)d * 64);
    for (int c = 0; c < 4; c++) {                   // 16-wide output chunks
        float o[16];
#pragma unroll
        for (int m = 0; m < 16; m++) o[m] = sb1b[c * 16 + m];
#pragma unroll
        for (int k = 0; k < 64; k++) {
            float hk = h[k];
#pragma unroll
            for (int q = 0; q < 4; q++) {
                float4 w = ((const float4*)sW1b)[k * 16 + c * 4 + q];
                o[q * 4 + 0] += hk * w.x; o[q * 4 + 1] += hk * w.y;
                o[q * 4 + 2] += hk * w.z; o[q * 4 + 3] += hk * w.w;
            }
        }
#pragma unroll
        for (int m = 0; m < 16; m++) {
            float v = fmaxf(o[m], 0.f);             // relu => v >= 0 => int-compare valid
            atomicMax(outp + c * 16 + m, __float_as_int(v));
        }
    }
}

// ---------------- squared norms ----------------
__global__ void k_sq() {
    int i = blockIdx.x * blockDim.x + threadIdx.x;   // 80*256 == N_PAD
    if (i >= N_PTS) { g_sq[i] = 1e30f; return; }     // pad keys never selected
    const float4* p = (const float4*)(g_x1 + (size_t)i * 64);
    float s = 0.f;
#pragma unroll
    for (int k = 0; k < 16; k++) { float4 v = p[k]; s += v.x * v.x + v.y * v.y + v.z * v.z + v.w * v.w; }
    g_sq[i] = s;
}

// ---------------- KNN stage A: distance GEMM, 64q x 128k tile, 4x8 micro, XOR swizzle ----
// block 256 = 16x16: x = k-col group (0..15), y = q-row group (0..15)
// thread: q rows 4y..4y+3, k cols x+16j (j=0..7)
__global__ void __launch_bounds__(256, 2) k_dist(int qbase) {
    __shared__ float sQ[64 * 64];    // 16 KB, XOR-16B swizzled rows
    __shared__ float sK[128 * 64];   // 32 KB

    const int tid = threadIdx.x;
    const int qrow0 = qbase + blockIdx.x * 64;
    const int krow0 = blockIdx.y * 128;

#pragma unroll
    for (int m = 0; m < 4; m++) {
        int idx = m * 256 + tid;                    // 1024 float4
        int r = idx >> 4, g = idx & 15;
        float4 v = ((const float4*)g_x1)[(size_t)(qrow0 + r) * 16 + g];
        *(float4*)(sQ + r * 64 + ((g ^ (r & 15)) << 2)) = v;
    }
#pragma unroll
    for (int m = 0; m < 8; m++) {
        int idx = m * 256 + tid;                    // 2048 float4
        int r = idx >> 4, g = idx & 15;
        float4 v = ((const float4*)g_x1)[(size_t)(krow0 + r) * 16 + g];
        *(float4*)(sK + r * 64 + ((g ^ (r & 15)) << 2)) = v;
    }
    __syncthreads();

    const int x = tid & 15;
    const int y = tid >> 4;
    const char* qb = (const char*)sQ;
    const char* kb = (const char*)sK;
    unsigned qoff[4], koff[8];
#pragma unroll
    for (int i = 0; i < 4; i++) { int r = 4 * y + i;  qoff[i] = r * 256 + ((r & 15) << 4); }
#pragma unroll
    for (int j = 0; j < 8; j++) { int r = x + 16 * j; koff[j] = r * 256 + ((r & 15) << 4); }

    unsigned long long acc[4][8];
#pragma unroll
    for (int i = 0; i < 4; i++)
#pragma unroll
        for (int j = 0; j < 8; j++) acc[i][j] = 0ull;

    for (int g16 = 0; g16 < 16; g16++) {            // 16B feature group
        unsigned t0 = (unsigned)(g16 << 4);
#pragma unroll
        for (int sub = 0; sub < 2; sub++) {         // 8B half (2 features)
            unsigned t = t0 | (sub << 3);
            unsigned long long qv[4], kv[8];
#pragma unroll
            for (int i = 0; i < 4; i++) qv[i] = *(const unsigned long long*)(qb + (qoff[i] ^ t));
#pragma unroll
            for (int j = 0; j < 8; j++) kv[j] = *(const unsigned long long*)(kb + (koff[j] ^ t));
#pragma unroll
            for (int i = 0; i < 4; i++)
#pragma unroll
                for (int j = 0; j < 8; j++) acc[i][j] = ffma2(qv[i], kv[j], acc[i][j]);
        }
    }

#pragma unroll
    for (int i = 0; i < 4; i++) {
        const float si = __ldg(&g_sq[qrow0 + 4 * y + i]);
        float* drow = g_D + (size_t)(blockIdx.x * 64 + 4 * y + i) * N_PAD + krow0;
#pragma unroll
        for (int j = 0; j < 8; j++) {
            float lo, hi; unpack2(lo, hi, acc[i][j]);
            float sk = __ldg(&g_sq[krow0 + x + 16 * j]);
            drow[x + 16 * j] = fmaf(-2.f, lo + hi, si + sk);
        }
    }
}

// ---------------- KNN stage B: threshold-gate + compact + exact top-16 ----------------
// 4 warps/block, 1 warp per row. grid = ROWBLK/4 blocks.
__global__ void __launch_bounds__(128) k_select(int qbase) {
    __shared__ unsigned long long sbuf[4][SCAP];    // 32 KB

    const int lane = threadIdx.x & 31;
    const int w    = threadIdx.x >> 5;
    const int rl   = blockIdx.x * 4 + w;
    const int gi   = qbase + rl;
    if (gi >= N_PTS) return;                        // warp-uniform (no block syncs below)

    const float4* Dp = (const float4*)(g_D + (size_t)rl * N_PAD);
    unsigned long long* buf = sbuf[w];
    const unsigned long long MAXK = 0xFFFFFFFFFFFFFFFFull;

    // ---- Phase A: exact 16th-smallest of first 1024 elements -> gate T0 ----
    unsigned long long a16[16];
#pragma unroll
    for (int m = 0; m < 16; m++) a16[m] = MAXK;
#pragma unroll
    for (int u = 0; u < 8; u++) {                   // lane's 32 sample elems
        float4 v = Dp[lane + 32 * u];
        float e[4] = {v.x, v.y, v.z, v.w};
        const int jb = 4 * (lane + 32 * u);
#pragma unroll
        for (int q = 0; q < 4; q++) {
            unsigned long long key = ((unsigned long long)sortable(e[q]) << 32) | (unsigned)(jb + q);
            unsigned long long mx = a16[0]; int slot = 0;
#pragma unroll
            for (int m = 1; m < 16; m++) if (a16[m] > mx) { mx = a16[m]; slot = m; }
            if (key < mx) {
#pragma unroll
                for (int m = 0; m < 16; m++) if (m == slot) a16[m] = key;
            }
        }
    }
    float T0f;
    {
        unsigned long long ext = MAXK;
        for (int sel = 0; sel < 16; sel++) {
            unsigned long long mn = a16[0]; int ms = 0;
#pragma unroll
            for (int m = 1; m < 16; m++) if (a16[m] < mn) { mn = a16[m]; ms = m; }
            unsigned long long gm = mn;
#pragma unroll
            for (int d = 1; d < 32; d <<= 1) {
                unsigned long long o = __shfl_xor_sync(0xFFFFFFFFu, gm, d);
                gm = (o < gm) ? o : gm;
            }
            if (gm == mn) {                          // unique winner (distinct j)
#pragma unroll
                for (int m = 0; m < 16; m++) if (m == ms) a16[m] = MAXK;
            }
            ext = gm;
        }
        T0f = unsortable((unsigned)(ext >> 32));     // sample-16th >= row-16th: valid gate
    }

    // ---- Phase B: compact all elems <= T0 into shared buffer (MLP-4 streaming) ----
    int cnt = 0;                                     // replicated warp count
    for (int u = 0; u < 160; u += 4) {
        float4 va[4];
#pragma unroll
        for (int k = 0; k < 4; k++) va[k] = Dp[lane + 32 * (u + k)];
#pragma unroll
        for (int k = 0; k < 4; k++) {
            float4 v = va[k];
            float mn4 = fminf(fminf(v.x, v.y), fminf(v.z, v.w));
            if (__any_sync(0xFFFFFFFFu, mn4 <= T0f)) {
                float e[4] = {v.x, v.y, v.z, v.w};
                const int jb = 4 * (lane + 32 * (u + k));
#pragma unroll
                for (int q = 0; q < 4; q++) {
                    bool p = (e[q] <= T0f);
                    unsigned b = __ballot_sync(0xFFFFFFFFu, p);
                    if (b) {
                        int off = __popc(b & ((1u << lane) - 1u));
                        if (p) {
                            int pos = cnt + off;
                            if (pos < SCAP)
                                buf[pos] = ((unsigned long long)sortable(e[q]) << 32) | (unsigned)(jb + q);
                        }
                        cnt += __popc(b);
                    }
                }
            }
        }
    }
    __syncwarp();

    if (cnt <= SCAP) {
        // ---- Phase C: exact top-16 from candidates (lex order == jax tie-break) ----
        const int n = cnt;                           // >= 16 (sample top-16 all <= T0)
        for (int sel = 0; sel < 16; sel++) {
            unsigned long long mn = MAXK; int mp = 0;
            for (int i = lane; i < n; i += 32) {
                unsigned long long kk = buf[i];
                if (kk < mn) { mn = kk; mp = i; }
            }
#pragma unroll
            for (int d = 1; d < 32; d <<= 1) {
                unsigned long long ok = __shfl_xor_sync(0xFFFFFFFFu, mn, d);
                int op = __shfl_xor_sync(0xFFFFFFFFu, mp, d);
                if (ok < mn) { mn = ok; mp = op; }
            }
            if (lane == 0) {
                buf[mp] = MAXK;
                g_nbr[gi * 16 + sel] = (int)(unsigned)(mn & 0xFFFFFFFFull);
            }
            __syncwarp();
        }
    } else {
        // ---- fallback (gate overflow, ~never): exact per-lane top-16 rescan ----
        unsigned long long best[16];
#pragma unroll
        for (int m = 0; m < 16; m++) best[m] = MAXK;
        unsigned long long worst = MAXK;
        for (int u = 0; u < 160; u++) {
            float4 v = Dp[lane + 32 * u];
            float e[4] = {v.x, v.y, v.z, v.w};
            const int jb = 4 * (lane + 32 * u);
#pragma unroll
            for (int q = 0; q < 4; q++) {
                unsigned long long key = ((unsigned long long)sortable(e[q]) << 32) | (unsigned)(jb + q);
                if (key < worst) {
                    unsigned long long mx = best[0]; int slot = 0;
#pragma unroll
                    for (int m = 1; m < 16; m++) if (best[m] > mx) { mx = best[m]; slot = m; }
#pragma unroll
                    for (int m = 0; m < 16; m++) if (m == slot) best[m] = key;
                    unsigned long long wk = best[0];
#pragma unroll
                    for (int m = 1; m < 16; m++) wk = (best[m] > wk) ? best[m] : wk;
                    worst = wk;
                }
            }
        }
        for (int sel = 0; sel < 16; sel++) {
            unsigned long long mn = best[0]; int ms = 0;
#pragma unroll
            for (int m = 1; m < 16; m++) if (best[m] < mn) { mn = best[m]; ms = m; }
            unsigned long long gm = mn;
#pragma unroll
            for (int d = 1; d < 32; d <<= 1) {
                unsigned long long o = __shfl_xor_sync(0xFFFFFFFFu, gm, d);
                gm = (o < gm) ? o : gm;
            }
            if (gm == mn) {
#pragma unroll
                for (int m = 0; m < 16; m++) if (m == ms) best[m] = MAXK;
            }
            if (lane == 0) g_nbr[gi * 16 + sel] = (int)(unsigned)(gm & 0xFFFFFFFFull);
        }
    }
}

// ---------------- stage 2: edgeconv (128->64 relu ->64 relu), max over 16 neighbors ----------------
__global__ void __launch_bounds__(128) k_conv2(const float* __restrict__ W2a,
                                               const float* __restrict__ b2a,
                                               const float* __restrict__ W2b,
                                               const float* __restrict__ b2b) {
    __shared__ float sW2a[128 * 64];    // 32 KB
    __shared__ float sW2b[64 * 64];     // 16 KB
    int tid = threadIdx.x;
    for (int m = tid; m < 128 * 64; m += 128) sW2a[m] = W2a[m];
    for (int m = tid; m < 64 * 64;  m += 128) sW2b[m] = W2b[m];
    __syncthreads();

    int gid = blockIdx.x * 128 + tid;   // 2500*128 == 320000 exactly
    int i  = gid >> 4;
    int jn = gid & 15;
    int j  = g_nbr[i * 16 + jn];
    const float4* xi4 = (const float4*)(g_x1 + (size_t)i * 64);
    const float4* xj4 = (const float4*)(g_x1 + (size_t)j * 64);

    float h[64];
#pragma unroll
    for (int f = 0; f < 64; f++) h[f] = __ldg(&b2a[f]);

#pragma unroll 4
    for (int k4 = 0; k4 < 16; k4++) {
        float4 A = xi4[k4], B = xj4[k4];
        float av[4] = {A.x, A.y, A.z, A.w};
        float dv[4] = {B.x - A.x, B.y - A.y, B.z - A.z, B.w - A.w};
#pragma unroll
        for (int s = 0; s < 4; s++) {
            int k = k4 * 4 + s;
            float a = av[s], dd = dv[s];
#pragma unroll
            for (int f4 = 0; f4 < 16; f4++) {
                float4 w1 = ((const float4*)sW2a)[k * 16 + f4];
                float4 w2 = ((const float4*)sW2a)[(64 + k) * 16 + f4];
                h[f4 * 4 + 0] += a * w1.x + dd * w2.x;
                h[f4 * 4 + 1] += a * w1.y + dd * w2.y;
                h[f4 * 4 + 2] += a * w1.z + dd * w2.z;
                h[f4 * 4 + 3] += a * w1.w + dd * w2.w;
            }
        }
    }
#pragma unroll
    for (int f = 0; f < 64; f++) h[f] = fmaxf(h[f], 0.f);

    for (int c = 0; c < 4; c++) {
        float o[16];
#pragma unroll
        for (int m = 0; m < 16; m++) o[m] = __ldg(&b2b[c * 16 + m]);
#pragma unroll
        for (int k = 0; k < 64; k++) {
            float hk = h[k];
#pragma unroll
            for (int q = 0; q < 4; q++) {
                float4 w = ((const float4*)sW2b)[k * 16 + c * 4 + q];
                o[q * 4 + 0] += hk * w.x; o[q * 4 + 1] += hk * w.y;
                o[q * 4 + 2] += hk * w.z; o[q * 4 + 3] += hk * w.w;
            }
        }
#pragma unroll
        for (int m = 0; m < 16; m++) {
            float v = fmaxf(o[m], 0.f);                              // relu before max
            v = fmaxf(v, __shfl_xor_sync(0xFFFFFFFFu, v, 1, 16));    // max over 16 neighbors
            v = fmaxf(v, __shfl_xor_sync(0xFFFFFFFFu, v, 2, 16));
            v = fmaxf(v, __shfl_xor_sync(0xFFFFFFFFu, v, 4, 16));
            v = fmaxf(v, __shfl_xor_sync(0xFFFFFFFFu, v, 8, 16));
            o[m] = v;
        }
        if (jn == 0) {
            float4* dst = (float4*)(g_x2 + (size_t)i * 64 + c * 16);
            dst[0] = make_float4(o[0],  o[1],  o[2],  o[3]);
            dst[1] = make_float4(o[4],  o[5],  o[6],  o[7]);
            dst[2] = make_float4(o[8],  o[9],  o[10], o[11]);
            dst[3] = make_float4(o[12], o[13], o[14], o[15]);
        }
    }
}

// ---------------- xe = x2 @ We + be, transposed-store per (i, r) ----------------
__global__ void __launch_bounds__(256) k_lin1(const float* __restrict__ We,
                                              const float* __restrict__ be) {
    __shared__ float sW[64 * 64];
    __shared__ float sb[64];
    int r = blockIdx.y, tid = threadIdx.x;
    for (int m = tid; m < 4096; m += 256) {
        int k = m >> 6, c = m & 63;
        sW[m] = We[k * 256 + r * 64 + c];
    }
    if (tid < 64) sb[tid] = be[r * 64 + tid];
    __syncthreads();

    int i = blockIdx.x * 256 + tid;
    if (i >= N_PTS) return;
    float x[64];
    const float4* xp = (const float4*)(g_x2 + (size_t)i * 64);
#pragma unroll
    for (int k4 = 0; k4 < 16; k4++) {
        float4 v = xp[k4];
        x[k4 * 4 + 0] = v.x; x[k4 * 4 + 1] = v.y; x[k4 * 4 + 2] = v.z; x[k4 * 4 + 3] = v.w;
    }
    float* outp = g_xs + ((size_t)r * N_PTS + i) * 64;
    for (int c = 0; c < 4; c++) {
        float o[16];
#pragma unroll
        for (int m = 0; m < 16; m++) o[m] = sb[c * 16 + m];
#pragma unroll
        for (int k = 0; k < 64; k++) {
            float xk = x[k];
#pragma unroll
            for (int q = 0; q < 4; q++) {
                float4 w = ((const float4*)sW)[k * 16 + c * 4 + q];
                o[q * 4 + 0] += xk * w.x; o[q * 4 + 1] += xk * w.y;
                o[q * 4 + 2] += xk * w.z; o[q * 4 + 3] += xk * w.w;
            }
        }
        float4* op = (float4*)(outp + c * 16);
        op[0] = make_float4(o[0],  o[1],  o[2],  o[3]);
        op[1] = make_float4(o[4],  o[5],  o[6],  o[7]);
        op[2] = make_float4(o[8],  o[9],  o[10], o[11]);
        op[3] = make_float4(o[12], o[13], o[14], o[15]);
    }
}

// ---------------- feat = xs @ Wp + bp ----------------
__global__ void __launch_bounds__(256) k_feat(const float* __restrict__ Wp,
                                              const float* __restrict__ bp) {
    __shared__ float sW[64 * 64];
    __shared__ float sb[64];
    int tid = threadIdx.x;
    for (int m = tid; m < 4096; m += 256) sW[m] = Wp[m];
    if (tid < 64) sb[tid] = bp[tid];
    __syncthreads();
    int i = blockIdx.x * 256 + tid;
    if (i >= N_PTS * 4) return;
    float x[64];
    const float4* xp = (const float4*)(g_xs + (size_t)i * 64);
#pragma unroll
    for (int k4 = 0; k4 < 16; k4++) {
        float4 v = xp[k4];
        x[k4 * 4 + 0] = v.x; x[k4 * 4 + 1] = v.y; x[k4 * 4 + 2] = v.z; x[k4 * 4 + 3] = v.w;
    }
    float* outp = g_feat + (size_t)i * 64;
    for (int c = 0; c < 4; c++) {
        float o[16];
#pragma unroll
        for (int m = 0; m < 16; m++) o[m] = sb[c * 16 + m];
#pragma unroll
        for (int k = 0; k < 64; k++) {
            float xk = x[k];
#pragma unroll
            for (int q = 0; q < 4; q++) {
                float4 w = ((const float4*)sW)[k * 16 + c * 4 + q];
                o[q * 4 + 0] += xk * w.x; o[q * 4 + 1] += xk * w.y;
                o[q * 4 + 2] += xk * w.z; o[q * 4 + 3] += xk * w.w;
            }
        }
        float4* op = (float4*)(outp + c * 16);
        op[0] = make_float4(o[0],  o[1],  o[2],  o[3]);
        op[1] = make_float4(o[4],  o[5],  o[6],  o[7]);
        op[2] = make_float4(o[8],  o[9],  o[10], o[11]);
        op[3] = make_float4(o[12], o[13], o[14], o[15]);
    }
}

// ---------------- head: h = relu(feat@Wr1+br1); out = h@Wr2 + br2 ----------------
__global__ void __launch_bounds__(256) k_head(float* __restrict__ out,
                                              const float* __restrict__ Wr1,
                                              const float* __restrict__ br1,
                                              const float* __restrict__ Wr2,
                                              const float* __restrict__ br2) {
    __shared__ float sW[64 * 64];
    __shared__ float sb[64];
    __shared__ float sW2[64 * 3];
    __shared__ float sb2[3];
    int tid = threadIdx.x;
    for (int m = tid; m < 4096; m += 256) sW[m] = Wr1[m];
    if (tid < 64) sb[tid] = br1[tid];
    if (tid < 192) sW2[tid] = Wr2[tid];
    if (tid < 3) sb2[tid] = br2[tid];
    __syncthreads();
    int i = blockIdx.x * 256 + tid;
    if (i >= N_PTS * 4) return;
    float x[64];
    const float4* xp = (const float4*)(g_feat + (size_t)i * 64);
#pragma unroll
    for (int k4 = 0; k4 < 16; k4++) {
        float4 v = xp[k4];
        x[k4 * 4 + 0] = v.x; x[k4 * 4 + 1] = v.y; x[k4 * 4 + 2] = v.z; x[k4 * 4 + 3] = v.w;
    }
    float o0 = sb2[0], o1 = sb2[1], o2 = sb2[2];
    for (int c = 0; c < 4; c++) {
        float o[16];
#pragma unroll
        for (int m = 0; m < 16; m++) o[m] = sb[c * 16 + m];
#pragma unroll
        for (int k = 0; k < 64; k++) {
            float xk = x[k];
#pragma unroll
            for (int q = 0; q < 4; q++) {
                float4 w = ((const float4*)sW)[k * 16 + c * 4 + q];
                o[q * 4 + 0] += xk * w.x; o[q * 4 + 1] += xk * w.y;
                o[q * 4 + 2] += xk * w.z; o[q * 4 + 3] += xk * w.w;
            }
        }
#pragma unroll
        for (int m = 0; m < 16; m++) {
            float hm = fmaxf(o[m], 0.f);
            int jrow = c * 16 + m;
            o0 += hm * sW2[jrow * 3 + 0];
            o1 += hm * sW2[jrow * 3 + 1];
            o2 += hm * sW2[jrow * 3 + 2];
        }
    }
    out[(size_t)i * 3 + 0] = o0;
    out[(size_t)i * 3 + 1] = o1;
    out[(size_t)i * 3 + 2] = o2;
}

// ---------------- launch ----------------
extern "C" void kernel_launch(void* const* d_in, const int* in_sizes, int n_in,
                              void* d_out, int out_size) {
    const float* dep = (const float*)d_in[0];
    const float* W1a = (const float*)d_in[1];
    const float* b1a = (const float*)d_in[2];
    const float* W1b = (const float*)d_in[3];
    const float* b1b = (const float*)d_in[4];
    const float* W2a = (const float*)d_in[5];
    const float* b2a = (const float*)d_in[6];
    const float* W2b = (const float*)d_in[7];
    const float* b2b = (const float*)d_in[8];
    const float* We  = (const float*)d_in[9];
    const float* be  = (const float*)d_in[10];
    const float* Wp  = (const float*)d_in[11];
    const float* bp  = (const float*)d_in[12];
    const float* Wr1 = (const float*)d_in[13];
    const float* br1 = (const float*)d_in[14];
    const float* Wr2 = (const float*)d_in[15];
    const float* br2 = (const float*)d_in[16];
    const int*   ei  = (const int*)d_in[17];
    float* out = (float*)d_out;

    k_zero<<<1280, 256>>>();                               // N_PAD*64/4 threads
    k_edge<<<1250, 256>>>(dep, ei, W1a, b1a, W1b, b1b);    // E threads exactly
    k_sq<<<80, 256>>>();                                   // N_PAD threads
    for (int b = 0; b < NBLK; b++) {
        k_dist<<<dim3(QT2, KT2), 256>>>(b * ROWBLK);
        k_select<<<ROWBLK / 4, 128>>>(b * ROWBLK);
    }
    k_conv2<<<2500, 128>>>(W2a, b2a, W2b, b2b);            // N*16 threads exactly
    k_lin1<<<dim3((N_PTS + 255) / 256, 4), 256>>>(We, be);
    k_feat<<<(N_PTS * 4 + 255) / 256, 256>>>(Wp, bp);
    k_head<<<(N_PTS * 4 + 255) / 256, 256>>>(out, Wr1, br1, Wr2, br2);
    (void)in_sizes; (void)n_in; (void)out_size;
}

// round 12
// speedup vs baseline: 2.4383x; 1.0629x over previous
#include <cuda_runtime.h>
#include <cstdint>

#define N_PTS 20000
#define N_PAD 20480          // 64*320: clean tiling for dist/select
#define E_EDG 320000
#define ROWBLK 2560          // query rows per dist/select pass
#define NBLK 8               // 8*2560 == N_PAD
#define QT3 20               // ROWBLK/128  (q tiles per dist launch)
#define KT3 320              // N_PAD/64    (k tiles per dist launch)
#define SSTR 68              // padded smem row stride (floats): conflict-free unit-stride rows
#define SCAP 1024            // per-warp candidate buffer

// ---------------- device scratch (no allocations allowed) ----------------
__device__ float g_x1[N_PAD * 64];            // node features after stage 1 (pad rows = 0)
__device__ float g_sq[N_PAD];                 // squared norms (pad = 1e30)
__device__ float g_D[(size_t)ROWBLK * N_PAD]; // distance row-block (210 MB)
__device__ int   g_nbr[N_PTS * 16];           // knn indices
__device__ float g_x2[N_PTS * 64];            // stage-2 features
__device__ float g_xs[N_PTS * 4 * 64];        // xe reshaped/transposed rows
__device__ float g_feat[N_PTS * 4 * 64];      // feat = xs@Wp+bp

// packed fp32x2 helpers (Blackwell FFMA2 path)
__device__ __forceinline__ unsigned long long ffma2(unsigned long long a,
                                                    unsigned long long b,
                                                    unsigned long long c) {
    unsigned long long d;
    asm("fma.rn.f32x2 %0, %1, %2, %3;" : "=l"(d) : "l"(a), "l"(b), "l"(c));
    return d;
}
__device__ __forceinline__ void unpack2(float& lo, float& hi, unsigned long long v) {
    asm("mov.b64 {%0, %1}, %2;" : "=f"(lo), "=f"(hi) : "l"(v));
}
// float <-> sortable-uint (exact order, handles negatives)
__device__ __forceinline__ unsigned sortable(float f) {
    unsigned b = __float_as_uint(f);
    return b ^ ((unsigned)((int)b >> 31) | 0x80000000u);
}
__device__ __forceinline__ float unsortable(unsigned u) {
    u = (u & 0x80000000u) ? (u ^ 0x80000000u) : ~u;
    return __uint_as_float(u);
}

// ---------------- zero x1 (incl. pad rows) ----------------
__global__ void k_zero() {
    int i = blockIdx.x * blockDim.x + threadIdx.x;   // 1280*256 == N_PAD*64/4 exactly
    ((float4*)g_x1)[i] = make_float4(0.f, 0.f, 0.f, 0.f);
}

// ---------------- stage 1: edge MLP (6->64 relu ->64 relu) + segment max ----------------
__global__ void __launch_bounds__(256) k_edge(const float* __restrict__ dep,
                                              const int*   __restrict__ ei,
                                              const float* __restrict__ W1a,
                                              const float* __restrict__ b1a,
                                              const float* __restrict__ W1b,
                                              const float* __restrict__ b1b) {
    __shared__ float sW1a[6 * 64];
    __shared__ float sW1b[64 * 64];
    __shared__ float sb1a[64];
    __shared__ float sb1b[64];
    int tid = threadIdx.x;
    for (int m = tid; m < 6 * 64; m += 256) sW1a[m] = W1a[m];
    for (int m = tid; m < 64 * 64; m += 256) sW1b[m] = W1b[m];
    if (tid < 64) { sb1a[tid] = b1a[tid]; sb1b[tid] = b1b[tid]; }
    __syncthreads();

    int e = blockIdx.x * 256 + tid;                 // grid 1250*256 == E exactly
    int s = ei[e];
    int d = ei[E_EDG + e];
    float xi0 = dep[d * 3], xi1 = dep[d * 3 + 1], xi2 = dep[d * 3 + 2];
    float in6[6];
    in6[0] = xi0; in6[1] = xi1; in6[2] = xi2;
    in6[3] = dep[s * 3] - xi0; in6[4] = dep[s * 3 + 1] - xi1; in6[5] = dep[s * 3 + 2] - xi2;

    float h[64];
#pragma unroll
    for (int f = 0; f < 64; f++) h[f] = sb1a[f];
#pragma unroll
    for (int k = 0; k < 6; k++) {
        float v = in6[k];
#pragma unroll
        for (int f4 = 0; f4 < 16; f4++) {
            float4 w = ((const float4*)sW1a)[k * 16 + f4];
            h[f4 * 4 + 0] += v * w.x; h[f4 * 4 + 1] += v * w.y;
            h[f4 * 4 + 2] += v * w.z; h[f4 * 4 + 3] += v * w.w;
        }
    }
#pragma unroll
    for (int f = 0; f < 64; f++) h[f] = fmaxf(h[f], 0.f);

    int* outp = (int*)(g_x1 + (size_t)d * 64);
    for (int c = 0; c < 4; c++) {                   // 16-wide output chunks
        float o[16];
#pragma unroll
        for (int m = 0; m < 16; m++) o[m] = sb1b[c * 16 + m];
#pragma unroll
        for (int k = 0; k < 64; k++) {
            float hk = h[k];
#pragma unroll
            for (int q = 0; q < 4; q++) {
                float4 w = ((const float4*)sW1b)[k * 16 + c * 4 + q];
                o[q * 4 + 0] += hk * w.x; o[q * 4 + 1] += hk * w.y;
                o[q * 4 + 2] += hk * w.z; o[q * 4 + 3] += hk * w.w;
            }
        }
#pragma unroll
        for (int m = 0; m < 16; m++) {
            float v = fmaxf(o[m], 0.f);             // relu => v >= 0 => int-compare valid
            atomicMax(outp + c * 16 + m, __float_as_int(v));
        }
    }
}

// ---------------- squared norms ----------------
__global__ void k_sq() {
    int i = blockIdx.x * blockDim.x + threadIdx.x;   // 80*256 == N_PAD
    if (i >= N_PTS) { g_sq[i] = 1e30f; return; }     // pad keys never selected
    const float4* p = (const float4*)(g_x1 + (size_t)i * 64);
    float s = 0.f;
#pragma unroll
    for (int k = 0; k < 16; k++) { float4 v = p[k]; s += v.x * v.x + v.y * v.y + v.z * v.z + v.w * v.w; }
    g_sq[i] = s;
}

// ---------------- KNN stage A: distance GEMM, 128q x 64k tile, warp=32x32, 4x8 micro ----
// 256 thr = 8 warps (qw 0..3, kw 0..1). lane: qa = lane>>2 (0..7), kb = lane&3 (0..3).
// thread q rows: qw*32 + qa + 8i (i<4); k cols: kw*32 + kb + 4j (j<8).
// Padded SSTR=68 rows: every LDS.128 group hits unit-stride rows -> conflict-free, imm offsets.
__global__ void __launch_bounds__(256, 2) k_dist(int qbase) {
    __shared__ __align__(16) float sQ[128 * SSTR];   // 34.8 KB
    __shared__ __align__(16) float sK[64 * SSTR];    // 17.4 KB

    const int tid = threadIdx.x;
    const int qrow0 = qbase + blockIdx.x * 128;
    const int krow0 = blockIdx.y * 64;

#pragma unroll
    for (int m = 0; m < 8; m++) {                    // Q: 2048 float4
        int idx = m * 256 + tid;
        int r = idx >> 4, g = idx & 15;
        *(float4*)(sQ + r * SSTR + g * 4) = ((const float4*)g_x1)[(size_t)(qrow0 + r) * 16 + g];
    }
#pragma unroll
    for (int m = 0; m < 4; m++) {                    // K: 1024 float4
        int idx = m * 256 + tid;
        int r = idx >> 4, g = idx & 15;
        *(float4*)(sK + r * SSTR + g * 4) = ((const float4*)g_x1)[(size_t)(krow0 + r) * 16 + g];
    }
    __syncthreads();

    const int lane = tid & 31;
    const int w  = tid >> 5;
    const int qw = w >> 1, kw = w & 1;
    const int qa = lane >> 2, kb = lane & 3;

    const char* qb = (const char*)sQ + (qw * 32 + qa) * (SSTR * 4);
    const char* kp = (const char*)sK + (kw * 32 + kb) * (SSTR * 4);

    unsigned long long acc[4][8];
#pragma unroll
    for (int i = 0; i < 4; i++)
#pragma unroll
        for (int j = 0; j < 8; j++) acc[i][j] = 0ull;

#pragma unroll 4
    for (int t = 0; t < 16; t++) {                   // 16B feature group (4 feats)
        ulonglong2 qv[4];
#pragma unroll
        for (int i = 0; i < 4; i++)
            qv[i] = *(const ulonglong2*)(qb + i * (8 * SSTR * 4) + t * 16);
#pragma unroll
        for (int jh = 0; jh < 2; jh++) {
            ulonglong2 kv[4];
#pragma unroll
            for (int j = 0; j < 4; j++)
                kv[j] = *(const ulonglong2*)(kp + (jh * 4 + j) * (4 * SSTR * 4) + t * 16);
#pragma unroll
            for (int i = 0; i < 4; i++)
#pragma unroll
                for (int j = 0; j < 4; j++) {
                    acc[i][jh * 4 + j] = ffma2(qv[i].x, kv[j].x, acc[i][jh * 4 + j]);
                    acc[i][jh * 4 + j] = ffma2(qv[i].y, kv[j].y, acc[i][jh * 4 + j]);
                }
        }
    }

#pragma unroll
    for (int i = 0; i < 4; i++) {
        const int rloc = qw * 32 + qa + 8 * i;
        const float si = __ldg(&g_sq[qrow0 + rloc]);
        float* drow = g_D + (size_t)(blockIdx.x * 128 + rloc) * N_PAD + krow0 + kw * 32;
#pragma unroll
        for (int j = 0; j < 8; j++) {
            float lo, hi; unpack2(lo, hi, acc[i][j]);
            float sk = __ldg(&g_sq[krow0 + kw * 32 + kb + 4 * j]);
            drow[kb + 4 * j] = fmaf(-2.f, lo + hi, si + sk);
        }
    }
}

// ---------------- KNN stage B: threshold-gate + compact + exact top-16 ----------------
// 4 warps/block, 1 warp per row. grid = ROWBLK/4 blocks.
__global__ void __launch_bounds__(128) k_select(int qbase) {
    __shared__ unsigned long long sbuf[4][SCAP];    // 32 KB

    const int lane = threadIdx.x & 31;
    const int w    = threadIdx.x >> 5;
    const int rl   = blockIdx.x * 4 + w;
    const int gi   = qbase + rl;
    if (gi >= N_PTS) return;                        // warp-uniform (no block syncs below)

    const float4* Dp = (const float4*)(g_D + (size_t)rl * N_PAD);
    unsigned long long* buf = sbuf[w];
    const unsigned long long MAXK = 0xFFFFFFFFFFFFFFFFull;

    // ---- Phase A: exact 16th-smallest of first 1024 elements -> gate T0 ----
    unsigned long long a16[16];
#pragma unroll
    for (int m = 0; m < 16; m++) a16[m] = MAXK;
#pragma unroll
    for (int u = 0; u < 8; u++) {                   // lane's 32 sample elems
        float4 v = Dp[lane + 32 * u];
        float e[4] = {v.x, v.y, v.z, v.w};
        const int jb = 4 * (lane + 32 * u);
#pragma unroll
        for (int q = 0; q < 4; q++) {
            unsigned long long key = ((unsigned long long)sortable(e[q]) << 32) | (unsigned)(jb + q);
            unsigned long long mx = a16[0]; int slot = 0;
#pragma unroll
            for (int m = 1; m < 16; m++) if (a16[m] > mx) { mx = a16[m]; slot = m; }
            if (key < mx) {
#pragma unroll
                for (int m = 0; m < 16; m++) if (m == slot) a16[m] = key;
            }
        }
    }
    float T0f;
    {
        unsigned long long ext = MAXK;
        for (int sel = 0; sel < 16; sel++) {
            unsigned long long mn = a16[0]; int ms = 0;
#pragma unroll
            for (int m = 1; m < 16; m++) if (a16[m] < mn) { mn = a16[m]; ms = m; }
            unsigned long long gm = mn;
#pragma unroll
            for (int d = 1; d < 32; d <<= 1) {
                unsigned long long o = __shfl_xor_sync(0xFFFFFFFFu, gm, d);
                gm = (o < gm) ? o : gm;
            }
            if (gm == mn) {                          // unique winner (distinct j)
#pragma unroll
                for (int m = 0; m < 16; m++) if (m == ms) a16[m] = MAXK;
            }
            ext = gm;
        }
        T0f = unsortable((unsigned)(ext >> 32));     // sample-16th >= row-16th: valid gate
    }

    // ---- Phase B: compact all elems <= T0 into shared buffer (MLP-4 streaming) ----
    int cnt = 0;                                     // replicated warp count
    for (int u = 0; u < 160; u += 4) {
        float4 va[4];
#pragma unroll
        for (int k = 0; k < 4; k++) va[k] = Dp[lane + 32 * (u + k)];
#pragma unroll
        for (int k = 0; k < 4; k++) {
            float4 v = va[k];
            float mn4 = fminf(fminf(v.x, v.y), fminf(v.z, v.w));
            if (__any_sync(0xFFFFFFFFu, mn4 <= T0f)) {
                float e[4] = {v.x, v.y, v.z, v.w};
                const int jb = 4 * (lane + 32 * (u + k));
#pragma unroll
                for (int q = 0; q < 4; q++) {
                    bool p = (e[q] <= T0f);
                    unsigned b = __ballot_sync(0xFFFFFFFFu, p);
                    if (b) {
                        int off = __popc(b & ((1u << lane) - 1u));
                        if (p) {
                            int pos = cnt + off;
                            if (pos < SCAP)
                                buf[pos] = ((unsigned long long)sortable(e[q]) << 32) | (unsigned)(jb + q);
                        }
                        cnt += __popc(b);
                    }
                }
            }
        }
    }
    __syncwarp();

    if (cnt <= SCAP) {
        // ---- Phase C: exact top-16 from candidates (lex order == jax tie-break) ----
        const int n = cnt;                           // >= 16 (sample top-16 all <= T0)
        for (int sel = 0; sel < 16; sel++) {
            unsigned long long mn = MAXK; int mp = 0;
            for (int i = lane; i < n; i += 32) {
                unsigned long long kk = buf[i];
                if (kk < mn) { mn = kk; mp = i; }
            }
#pragma unroll
            for (int d = 1; d < 32; d <<= 1) {
                unsigned long long ok = __shfl_xor_sync(0xFFFFFFFFu, mn, d);
                int op = __shfl_xor_sync(0xFFFFFFFFu, mp, d);
                if (ok < mn) { mn = ok; mp = op; }
            }
            if (lane == 0) {
                buf[mp] = MAXK;
                g_nbr[gi * 16 + sel] = (int)(unsigned)(mn & 0xFFFFFFFFull);
            }
            __syncwarp();
        }
    } else {
        // ---- fallback (gate overflow, ~never): exact per-lane top-16 rescan ----
        unsigned long long best[16];
#pragma unroll
        for (int m = 0; m < 16; m++) best[m] = MAXK;
        unsigned long long worst = MAXK;
        for (int u = 0; u < 160; u++) {
            float4 v = Dp[lane + 32 * u];
            float e[4] = {v.x, v.y, v.z, v.w};
            const int jb = 4 * (lane + 32 * u);
#pragma unroll
            for (int q = 0; q < 4; q++) {
                unsigned long long key = ((unsigned long long)sortable(e[q]) << 32) | (unsigned)(jb + q);
                if (key < worst) {
                    unsigned long long mx = best[0]; int slot = 0;
#pragma unroll
                    for (int m = 1; m < 16; m++) if (best[m] > mx) { mx = best[m]; slot = m; }
#pragma unroll
                    for (int m = 0; m < 16; m++) if (m == slot) best[m] = key;
                    unsigned long long wk = best[0];
#pragma unroll
                    for (int m = 1; m < 16; m++) wk = (best[m] > wk) ? best[m] : wk;
                    worst = wk;
                }
            }
        }
        for (int sel = 0; sel < 16; sel++) {
            unsigned long long mn = best[0]; int ms = 0;
#pragma unroll
            for (int m = 1; m < 16; m++) if (best[m] < mn) { mn = best[m]; ms = m; }
            unsigned long long gm = mn;
#pragma unroll
            for (int d = 1; d < 32; d <<= 1) {
                unsigned long long o = __shfl_xor_sync(0xFFFFFFFFu, gm, d);
                gm = (o < gm) ? o : gm;
            }
            if (gm == mn) {
#pragma unroll
                for (int m = 0; m < 16; m++) if (m == ms) best[m] = MAXK;
            }
            if (lane == 0) g_nbr[gi * 16 + sel] = (int)(unsigned)(gm & 0xFFFFFFFFull);
        }
    }
}

// ---------------- stage 2: edgeconv (128->64 relu ->64 relu), max over 16 neighbors ----------------
__global__ void __launch_bounds__(128) k_conv2(const float* __restrict__ W2a,
                                               const float* __restrict__ b2a,
                                               const float* __restrict__ W2b,
                                               const float* __restrict__ b2b) {
    __shared__ float sW2a[128 * 64];    // 32 KB
    __shared__ float sW2b[64 * 64];     // 16 KB
    int tid = threadIdx.x;
    for (int m = tid; m < 128 * 64; m += 128) sW2a[m] = W2a[m];
    for (int m = tid; m < 64 * 64;  m += 128) sW2b[m] = W2b[m];
    __syncthreads();

    int gid = blockIdx.x * 128 + tid;   // 2500*128 == 320000 exactly
    int i  = gid >> 4;
    int jn = gid & 15;
    int j  = g_nbr[i * 16 + jn];
    const float4* xi4 = (const float4*)(g_x1 + (size_t)i * 64);
    const float4* xj4 = (const float4*)(g_x1 + (size_t)j * 64);

    float h[64];
#pragma unroll
    for (int f = 0; f < 64; f++) h[f] = __ldg(&b2a[f]);

#pragma unroll 4
    for (int k4 = 0; k4 < 16; k4++) {
        float4 A = xi4[k4], B = xj4[k4];
        float av[4] = {A.x, A.y, A.z, A.w};
        float dv[4] = {B.x - A.x, B.y - A.y, B.z - A.z, B.w - A.w};
#pragma unroll
        for (int s = 0; s < 4; s++) {
            int k = k4 * 4 + s;
            float a = av[s], dd = dv[s];
#pragma unroll
            for (int f4 = 0; f4 < 16; f4++) {
                float4 w1 = ((const float4*)sW2a)[k * 16 + f4];
                float4 w2 = ((const float4*)sW2a)[(64 + k) * 16 + f4];
                h[f4 * 4 + 0] += a * w1.x + dd * w2.x;
                h[f4 * 4 + 1] += a * w1.y + dd * w2.y;
                h[f4 * 4 + 2] += a * w1.z + dd * w2.z;
                h[f4 * 4 + 3] += a * w1.w + dd * w2.w;
            }
        }
    }
#pragma unroll
    for (int f = 0; f < 64; f++) h[f] = fmaxf(h[f], 0.f);

    for (int c = 0; c < 4; c++) {
        float o[16];
#pragma unroll
        for (int m = 0; m < 16; m++) o[m] = __ldg(&b2b[c * 16 + m]);
#pragma unroll
        for (int k = 0; k < 64; k++) {
            float hk = h[k];
#pragma unroll
            for (int q = 0; q < 4; q++) {
                float4 w = ((const float4*)sW2b)[k * 16 + c * 4 + q];
                o[q * 4 + 0] += hk * w.x; o[q * 4 + 1] += hk * w.y;
                o[q * 4 + 2] += hk * w.z; o[q * 4 + 3] += hk * w.w;
            }
        }
#pragma unroll
        for (int m = 0; m < 16; m++) {
            float v = fmaxf(o[m], 0.f);                              // relu before max
            v = fmaxf(v, __shfl_xor_sync(0xFFFFFFFFu, v, 1, 16));    // max over 16 neighbors
            v = fmaxf(v, __shfl_xor_sync(0xFFFFFFFFu, v, 2, 16));
            v = fmaxf(v, __shfl_xor_sync(0xFFFFFFFFu, v, 4, 16));
            v = fmaxf(v, __shfl_xor_sync(0xFFFFFFFFu, v, 8, 16));
            o[m] = v;
        }
        if (jn == 0) {
            float4* dst = (float4*)(g_x2 + (size_t)i * 64 + c * 16);
            dst[0] = make_float4(o[0],  o[1],  o[2],  o[3]);
            dst[1] = make_float4(o[4],  o[5],  o[6],  o[7]);
            dst[2] = make_float4(o[8],  o[9],  o[10], o[11]);
            dst[3] = make_float4(o[12], o[13], o[14], o[15]);
        }
    }
}

// ---------------- xe = x2 @ We + be, transposed-store per (i, r) ----------------
__global__ void __launch_bounds__(256) k_lin1(const float* __restrict__ We,
                                              const float* __restrict__ be) {
    __shared__ float sW[64 * 64];
    __shared__ float sb[64];
    int r = blockIdx.y, tid = threadIdx.x;
    for (int m = tid; m < 4096; m += 256) {
        int k = m >> 6, c = m & 63;
        sW[m] = We[k * 256 + r * 64 + c];
    }
    if (tid < 64) sb[tid] = be[r * 64 + tid];
    __syncthreads();

    int i = blockIdx.x * 256 + tid;
    if (i >= N_PTS) return;
    float x[64];
    const float4* xp = (const float4*)(g_x2 + (size_t)i * 64);
#pragma unroll
    for (int k4 = 0; k4 < 16; k4++) {
        float4 v = xp[k4];
        x[k4 * 4 + 0] = v.x; x[k4 * 4 + 1] = v.y; x[k4 * 4 + 2] = v.z; x[k4 * 4 + 3] = v.w;
    }
    float* outp = g_xs + ((size_t)r * N_PTS + i) * 64;
    for (int c = 0; c < 4; c++) {
        float o[16];
#pragma unroll
        for (int m = 0; m < 16; m++) o[m] = sb[c * 16 + m];
#pragma unroll
        for (int k = 0; k < 64; k++) {
            float xk = x[k];
#pragma unroll
            for (int q = 0; q < 4; q++) {
                float4 w = ((const float4*)sW)[k * 16 + c * 4 + q];
                o[q * 4 + 0] += xk * w.x; o[q * 4 + 1] += xk * w.y;
                o[q * 4 + 2] += xk * w.z; o[q * 4 + 3] += xk * w.w;
            }
        }
        float4* op = (float4*)(outp + c * 16);
        op[0] = make_float4(o[0],  o[1],  o[2],  o[3]);
        op[1] = make_float4(o[4],  o[5],  o[6],  o[7]);
        op[2] = make_float4(o[8],  o[9],  o[10], o[11]);
        op[3] = make_float4(o[12], o[13], o[14], o[15]);
    }
}

// ---------------- feat = xs @ Wp + bp ----------------
__global__ void __launch_bounds__(256) k_feat(const float* __restrict__ Wp,
                                              const float* __restrict__ bp) {
    __shared__ float sW[64 * 64];
    __shared__ float sb[64];
    int tid = threadIdx.x;
    for (int m = tid; m < 4096; m += 256) sW[m] = Wp[m];
    if (tid < 64) sb[tid] = bp[tid];
    __syncthreads();
    int i = blockIdx.x * 256 + tid;
    if (i >= N_PTS * 4) return;
    float x[64];
    const float4* xp = (const float4*)(g_xs + (size_t)i * 64);
#pragma unroll
    for (int k4 = 0; k4 < 16; k4++) {
        float4 v = xp[k4];
        x[k4 * 4 + 0] = v.x; x[k4 * 4 + 1] = v.y; x[k4 * 4 + 2] = v.z; x[k4 * 4 + 3] = v.w;
    }
    float* outp = g_feat + (size_t)i * 64;
    for (int c = 0; c < 4; c++) {
        float o[16];
#pragma unroll
        for (int m = 0; m < 16; m++) o[m] = sb[c * 16 + m];
#pragma unroll
        for (int k = 0; k < 64; k++) {
            float xk = x[k];
#pragma unroll
            for (int q = 0; q < 4; q++) {
                float4 w = ((const float4*)sW)[k * 16 + c * 4 + q];
                o[q * 4 + 0] += xk * w.x; o[q * 4 + 1] += xk * w.y;
                o[q * 4 + 2] += xk * w.z; o[q * 4 + 3] += xk * w.w;
            }
        }
        float4* op = (float4*)(outp + c * 16);
        op[0] = make_float4(o[0],  o[1],  o[2],  o[3]);
        op[1] = make_float4(o[4],  o[5],  o[6],  o[7]);
        op[2] = make_float4(o[8],  o[9],  o[10], o[11]);
        op[3] = make_float4(o[12], o[13], o[14], o[15]);
    }
}

// ---------------- head: h = relu(feat@Wr1+br1); out = h@Wr2 + br2 ----------------
__global__ void __launch_bounds__(256) k_head(float* __restrict__ out,
                                              const float* __restrict__ Wr1,
                                              const float* __restrict__ br1,
                                              const float* __restrict__ Wr2,
                                              const float* __restrict__ br2) {
    __shared__ float sW[64 * 64];
    __shared__ float sb[64];
    __shared__ float sW2[64 * 3];
    __shared__ float sb2[3];
    int tid = threadIdx.x;
    for (int m = tid; m < 4096; m += 256) sW[m] = Wr1[m];
    if (tid < 64) sb[tid] = br1[tid];
    if (tid < 192) sW2[tid] = Wr2[tid];
    if (tid < 3) sb2[tid] = br2[tid];
    __syncthreads();
    int i = blockIdx.x * 256 + tid;
    if (i >= N_PTS * 4) return;
    float x[64];
    const float4* xp = (const float4*)(g_feat + (size_t)i * 64);
#pragma unroll
    for (int k4 = 0; k4 < 16; k4++) {
        float4 v = xp[k4];
        x[k4 * 4 + 0] = v.x; x[k4 * 4 + 1] = v.y; x[k4 * 4 + 2] = v.z; x[k4 * 4 + 3] = v.w;
    }
    float o0 = sb2[0], o1 = sb2[1], o2 = sb2[2];
    for (int c = 0; c < 4; c++) {
        float o[16];
#pragma unroll
        for (int m = 0; m < 16; m++) o[m] = sb[c * 16 + m];
#pragma unroll
        for (int k = 0; k < 64; k++) {
            float xk = x[k];
#pragma unroll
            for (int q = 0; q < 4; q++) {
                float4 w = ((const float4*)sW)[k * 16 + c * 4 + q];
                o[q * 4 + 0] += xk * w.x; o[q * 4 + 1] += xk * w.y;
                o[q * 4 + 2] += xk * w.z; o[q * 4 + 3] += xk * w.w;
            }
        }
#pragma unroll
        for (int m = 0; m < 16; m++) {
            float hm = fmaxf(o[m], 0.f);
            int jrow = c * 16 + m;
            o0 += hm * sW2[jrow * 3 + 0];
            o1 += hm * sW2[jrow * 3 + 1];
            o2 += hm * sW2[jrow * 3 + 2];
        }
    }
    out[(size_t)i * 3 + 0] = o0;
    out[(size_t)i * 3 + 1] = o1;
    out[(size_t)i * 3 + 2] = o2;
}

// ---------------- launch ----------------
extern "C" void kernel_launch(void* const* d_in, const int* in_sizes, int n_in,
                              void* d_out, int out_size) {
    const float* dep = (const float*)d_in[0];
    const float* W1a = (const float*)d_in[1];
    const float* b1a = (const float*)d_in[2];
    const float* W1b = (const float*)d_in[3];
    const float* b1b = (const float*)d_in[4];
    const float* W2a = (const float*)d_in[5];
    const float* b2a = (const float*)d_in[6];
    const float* W2b = (const float*)d_in[7];
    const float* b2b = (const float*)d_in[8];
    const float* We  = (const float*)d_in[9];
    const float* be  = (const float*)d_in[10];
    const float* Wp  = (const float*)d_in[11];
    const float* bp  = (const float*)d_in[12];
    const float* Wr1 = (const float*)d_in[13];
    const float* br1 = (const float*)d_in[14];
    const float* Wr2 = (const float*)d_in[15];
    const float* br2 = (const float*)d_in[16];
    const int*   ei  = (const int*)d_in[17];
    float* out = (float*)d_out;

    k_zero<<<1280, 256>>>();                               // N_PAD*64/4 threads
    k_edge<<<1250, 256>>>(dep, ei, W1a, b1a, W1b, b1b);    // E threads exactly
    k_sq<<<80, 256>>>();                                   // N_PAD threads
    for (int b = 0; b < NBLK; b++) {
        k_dist<<<dim3(QT3, KT3), 256>>>(b * ROWBLK);
        k_select<<<ROWBLK / 4, 128>>>(b * ROWBLK);
    }
    k_conv2<<<2500, 128>>>(W2a, b2a, W2b, b2b);            // N*16 threads exactly
    k_lin1<<<dim3((N_PTS + 255) / 256, 4), 256>>>(We, be);
    k_feat<<<(N_PTS * 4 + 255) / 256, 256>>>(Wp, bp);
    k_head<<<(N_PTS * 4 + 255) / 256, 256>>>(out, Wr1, br1, Wr2, br2);
    (void)in_sizes; (void)n_in; (void)out_size;
}